// round 4
// baseline (speedup 1.0000x reference)
#include <cuda_runtime.h>
#include <math_constants.h>

#define H 1024
#define S 32768
#define GRID 512               // one full wave: <=4 CTAs/SM on 148 SMs
#define ROWS_PER_BLK (S / GRID) // 64 rows per block, 8 per warp
#define D_SLICE 8              // d-rows per partial slice (128 slices)

// Scratch (no allocations allowed)
__device__ float g_vpart[128 * H];
__device__ float g_v[H];
__device__ float g_scores[S];
__device__ float g_bmax[GRID];
__device__ float g_bsum[GRID];
__device__ unsigned g_bar;     // zero-initialized; self-resetting
__device__ unsigned g_done;

__device__ __forceinline__ void grid_sync(unsigned target) {
    __syncthreads();
    __threadfence();
    if (threadIdx.x == 0) {
        atomicAdd(&g_bar, 1u);
        while (*(volatile unsigned*)&g_bar < target) __nanosleep(64);
    }
    __syncthreads();
}

__global__ __launch_bounds__(256, 4) void fused_kernel(
    const float* __restrict__ W,
    const float* __restrict__ hidden,
    const float* __restrict__ enc,
    float* __restrict__ out)
{
    __shared__ float sv[H];
    __shared__ float s_sc[ROWS_PER_BLK];
    __shared__ float red[256];

    const int tid  = threadIdx.x;
    const int warp = tid >> 5;
    const int lane = tid & 31;
    const int b    = blockIdx.x;

    // ---------------- P0: v partials (coalesced 4 MB read of W) ------------
    {
        const int hc = b >> 7;            // 0..3  (h chunk of 256)
        const int ds = b & 127;           // 0..127 (d slice of 8)
        const int h  = hc * 256 + tid;
        const int d0 = ds * D_SLICE;
        float acc = 0.f;
#pragma unroll
        for (int dd = 0; dd < D_SLICE; dd++)
            acc += W[(size_t)(d0 + dd) * H + h] * __ldg(&hidden[d0 + dd]);
        g_vpart[ds * H + h] = acc;
    }
    grid_sync(GRID);

    // ---------------- P1: reduce partials -> g_v (4 blocks, L2-hot) -------
    if (b < 4) {
        const int h = b * 256 + tid;
        float acc = 0.f;
#pragma unroll 16
        for (int i = 0; i < 128; i++) acc += g_vpart[i * H + h];
        g_v[h] = acc;
    }
    grid_sync(2 * GRID);

    // ---------------- P2: scores = enc . v  (128 MB stream) ---------------
    reinterpret_cast<float4*>(sv)[tid] = reinterpret_cast<const float4*>(g_v)[tid];
    __syncthreads();

    const float4* v4 = reinterpret_cast<const float4*>(sv);
#pragma unroll 2
    for (int rr = 0; rr < 8; rr++) {
        const size_t row = (size_t)b * ROWS_PER_BLK + warp * 8 + rr;
        const float4* r = reinterpret_cast<const float4*>(enc + row * H);
        float acc = 0.f;
#pragma unroll
        for (int k = 0; k < 8; k++) {
            float4 e  = r[lane + k * 32];
            float4 vv = v4[lane + k * 32];
            acc += e.x * vv.x + e.y * vv.y + e.z * vv.z + e.w * vv.w;
        }
#pragma unroll
        for (int o = 16; o > 0; o >>= 1) acc += __shfl_xor_sync(0xFFFFFFFFu, acc, o);
        if (lane == 0) {
            g_scores[row] = acc;
            s_sc[warp * 8 + rr] = acc;
        }
    }
    __syncthreads();

    // block (max, expsum) over its 64 scores — warp 0
    if (warp == 0) {
        float v0 = s_sc[lane];
        float v1 = s_sc[lane + 32];
        float m = fmaxf(v0, v1);
#pragma unroll
        for (int o = 16; o > 0; o >>= 1) m = fmaxf(m, __shfl_xor_sync(0xFFFFFFFFu, m, o));
        float e = __expf(v0 - m) + __expf(v1 - m);
#pragma unroll
        for (int o = 16; o > 0; o >>= 1) e += __shfl_xor_sync(0xFFFFFFFFu, e, o);
        if (lane == 0) {
            g_bmax[b] = m;
            g_bsum[b] = e;
        }
    }
    grid_sync(3 * GRID);

    // ---------------- P3: redundant pair-reduce + normalize ---------------
    const float pm0 = g_bmax[tid];
    const float pm1 = g_bmax[tid + 256];
    const float ps0 = g_bsum[tid];
    const float ps1 = g_bsum[tid + 256];

    red[tid] = fmaxf(pm0, pm1);
    __syncthreads();
#pragma unroll
    for (int s = 128; s > 0; s >>= 1) {
        if (tid < s) red[tid] = fmaxf(red[tid], red[tid + s]);
        __syncthreads();
    }
    const float M = red[0];
    __syncthreads();

    red[tid] = ps0 * __expf(pm0 - M) + ps1 * __expf(pm1 - M);
    __syncthreads();
#pragma unroll
    for (int s = 128; s > 0; s >>= 1) {
        if (tid < s) red[tid] += red[tid + s];
        __syncthreads();
    }
    const float inv = 1.0f / red[0];

    // normalize this block's 64 rows (scores are L2-resident)
    if (tid < ROWS_PER_BLK) {
        const int i = b * ROWS_PER_BLK + tid;
        out[i] = __expf(g_scores[i] - M) * inv;
    }

    // ---------------- barrier reset for next graph replay ------------------
    __threadfence();
    __syncthreads();
    if (tid == 0) {
        unsigned d = atomicAdd(&g_done, 1u) + 1;
        if (d == GRID) {
            g_bar = 0;
            g_done = 0;
            __threadfence();
        }
    }
}

// ---------------------------------------------------------------------------
extern "C" void kernel_launch(void* const* d_in, const int* in_sizes, int n_in,
                              void* d_out, int out_size) {
    const float* hidden = (const float*)d_in[0];   // [H]
    const float* enc    = (const float*)d_in[1];   // [S, H]
    const float* W      = (const float*)d_in[2];   // [H, H]
    float* out          = (float*)d_out;           // [S]

    fused_kernel<<<GRID, 256>>>(W, hidden, enc, out);
}

// round 5
// speedup vs baseline: 1.0101x; 1.0101x over previous
#include <cuda_runtime.h>
#include <math_constants.h>

#define H 1024
#define S 32768
#define D_SLICES 64

#define BLK 256                 // scores block: 8 warps
#define TILE_ROWS 8             // rows per pipeline stage (32 KB)
#define STAGES 2
#define TILE_F4 (TILE_ROWS * H / 4)     // float4 per tile = 2048
#define SCORE_GRID 1024
#define TILES_PER_BLK (S / TILE_ROWS / SCORE_GRID)  // 4
#define SMEM_DYN (STAGES * TILE_F4 * 16)            // 65536 B

// Scratch (no allocations allowed)
__device__ float g_vpart[D_SLICES * H];
__device__ float g_v[H];
__device__ float g_scores[S];
__device__ float g_bmax[SCORE_GRID];
__device__ float g_bsum[SCORE_GRID];
__device__ float g_M;
__device__ float g_inv;
__device__ unsigned g_cnt;      // zero-init; self-resetting

// ---------------------------------------------------------------------------
// K1: partial v[h] over 16-row d-slices of W. grid (4, 64), block 256.
// ---------------------------------------------------------------------------
__global__ void v_partial_kernel(const float* __restrict__ W,
                                 const float* __restrict__ hidden) {
    const int h  = blockIdx.x * 256 + threadIdx.x;
    const int d0 = blockIdx.y * (H / D_SLICES);
    float acc = 0.f;
#pragma unroll
    for (int dd = 0; dd < H / D_SLICES; dd++)
        acc += W[(size_t)(d0 + dd) * H + h] * __ldg(&hidden[d0 + dd]);
    g_vpart[blockIdx.y * H + h] = acc;
}

// ---------------------------------------------------------------------------
// K2: reduce partials -> g_v. grid 4, block 256.
// ---------------------------------------------------------------------------
__global__ void v_reduce_kernel() {
    const int h = blockIdx.x * 256 + threadIdx.x;
    float acc = 0.f;
#pragma unroll 16
    for (int i = 0; i < D_SLICES; i++) acc += g_vpart[i * H + h];
    g_v[h] = acc;
}

// ---------------------------------------------------------------------------
// K3: scores = enc . v  via cp.async double-buffered smem pipeline.
// grid 1024, block 256 (8 warps). Warp w computes row w of each 8-row tile.
// Last-finishing block reduces the 1024 (m,S) pairs -> g_M, g_inv.
// ---------------------------------------------------------------------------
__global__ __launch_bounds__(BLK) void scores_kernel(const float* __restrict__ enc) {
    extern __shared__ float4 tile[];     // [STAGES][TILE_F4]
    __shared__ float s_pm[8], s_ps[8];
    __shared__ float red[BLK];
    __shared__ unsigned s_last;

    const int tid  = threadIdx.x;
    const int warp = tid >> 5;
    const int lane = tid & 31;
    const int b    = blockIdx.x;
    const int t0   = b * TILES_PER_BLK;

    // v resident in registers: 8 float4 per lane (pattern identical for all rows)
    float4 vr[8];
    const float4* v4 = reinterpret_cast<const float4*>(g_v);
#pragma unroll
    for (int k = 0; k < 8; k++) vr[k] = v4[lane + k * 32];

    const float4* encf4 = reinterpret_cast<const float4*>(enc);

#define PREFETCH(stage, t_idx)                                                  \
    {                                                                           \
        const float4* src = encf4 + (size_t)(t_idx) * TILE_F4;                  \
        float4* dst = tile + (stage) * TILE_F4;                                 \
        _Pragma("unroll")                                                       \
        for (int i = 0; i < TILE_F4 / BLK; i++) {                               \
            int c = tid + i * BLK;                                              \
            unsigned sa = (unsigned)__cvta_generic_to_shared(dst + c);          \
            asm volatile("cp.async.cg.shared.global [%0], [%1], 16;"            \
                         :: "r"(sa), "l"(src + c));                             \
        }                                                                       \
        asm volatile("cp.async.commit_group;");                                 \
    }

    PREFETCH(0, t0)
    PREFETCH(1, t0 + 1)

    float m_run = -CUDART_INF_F;
    float s_run = 0.f;

#pragma unroll
    for (int t = 0; t < TILES_PER_BLK; t++) {
        asm volatile("cp.async.wait_group 1;");
        __syncthreads();

        const float4* rowp = tile + (t & 1) * TILE_F4 + warp * (H / 4);
        float acc = 0.f;
#pragma unroll
        for (int k = 0; k < 8; k++) {
            float4 e = rowp[lane + k * 32];
            acc += e.x * vr[k].x + e.y * vr[k].y + e.z * vr[k].z + e.w * vr[k].w;
        }
#pragma unroll
        for (int o = 16; o > 0; o >>= 1) acc += __shfl_xor_sync(0xFFFFFFFFu, acc, o);

        if (lane == 0) g_scores[(size_t)(t0 + t) * TILE_ROWS + warp] = acc;

        // running (max, expsum) per warp — acc is broadcast to all lanes
        float mn = fmaxf(m_run, acc);
        s_run = s_run * __expf(m_run - mn) + __expf(acc - mn);
        m_run = mn;

        __syncthreads();   // everyone done reading this buffer
        if (t + STAGES < TILES_PER_BLK) {
            PREFETCH(t & 1, t0 + t + STAGES)
        } else {
            asm volatile("cp.async.commit_group;");   // empty group keeps wait counts sane
        }
    }

    if (lane == 0) { s_pm[warp] = m_run; s_ps[warp] = s_run; }
    __syncthreads();

    // warp 0 combines the 8 warp pairs -> block pair
    if (tid == 0) {
        float m = s_pm[0];
#pragma unroll
        for (int i = 1; i < 8; i++) m = fmaxf(m, s_pm[i]);
        float s = 0.f;
#pragma unroll
        for (int i = 0; i < 8; i++) s += s_ps[i] * __expf(s_pm[i] - m);
        g_bmax[b] = m;
        g_bsum[b] = s;
        __threadfence();
        unsigned prev = atomicAdd(&g_cnt, 1u);
        s_last = (prev == (unsigned)gridDim.x - 1u) ? 1u : 0u;
    }
    __syncthreads();

    // last-finishing block reduces all pairs (fixed order -> deterministic)
    if (s_last) {
        __threadfence();
        float pm[SCORE_GRID / BLK], ps[SCORE_GRID / BLK];
        float m = -CUDART_INF_F;
#pragma unroll
        for (int k = 0; k < SCORE_GRID / BLK; k++) {
            pm[k] = g_bmax[tid + k * BLK];
            ps[k] = g_bsum[tid + k * BLK];
            m = fmaxf(m, pm[k]);
        }
        red[tid] = m;
        __syncthreads();
#pragma unroll
        for (int s = 128; s > 0; s >>= 1) {
            if (tid < s) red[tid] = fmaxf(red[tid], red[tid + s]);
            __syncthreads();
        }
        const float M = red[0];
        __syncthreads();

        float sum = 0.f;
#pragma unroll
        for (int k = 0; k < SCORE_GRID / BLK; k++)
            sum += ps[k] * __expf(pm[k] - M);
        red[tid] = sum;
        __syncthreads();
#pragma unroll
        for (int s = 128; s > 0; s >>= 1) {
            if (tid < s) red[tid] += red[tid + s];
            __syncthreads();
        }
        if (tid == 0) {
            g_M = M;
            g_inv = 1.0f / red[0];
            g_cnt = 0;                 // reset for next graph replay
            __threadfence();
        }
    }
#undef PREFETCH
}

// ---------------------------------------------------------------------------
// K4: pure-stream normalize. grid 128, block 256.
// ---------------------------------------------------------------------------
__global__ __launch_bounds__(256) void normalize_kernel(float* __restrict__ out) {
    const int i = blockIdx.x * 256 + threadIdx.x;
    out[i] = __expf(g_scores[i] - g_M) * g_inv;
}

// ---------------------------------------------------------------------------
extern "C" void kernel_launch(void* const* d_in, const int* in_sizes, int n_in,
                              void* d_out, int out_size) {
    const float* hidden = (const float*)d_in[0];   // [H]
    const float* enc    = (const float*)d_in[1];   // [S, H]
    const float* W      = (const float*)d_in[2];   // [H, H]
    float* out          = (float*)d_out;           // [S]

    cudaFuncSetAttribute(scores_kernel,
                         cudaFuncAttributeMaxDynamicSharedMemorySize, SMEM_DYN);

    v_partial_kernel<<<dim3(H / 256, D_SLICES), 256>>>(W, hidden);
    v_reduce_kernel<<<H / 256, 256>>>();
    scores_kernel<<<SCORE_GRID, BLK, SMEM_DYN>>>(enc);
    normalize_kernel<<<S / 256, 256>>>(out);
}

// round 6
// speedup vs baseline: 1.2450x; 1.2325x over previous
#include <cuda_runtime.h>
#include <math_constants.h>

#define H 1024
#define S 32768
#define GRID 256
#define BLK 256
#define ROWS_PER_BLK (S / GRID)          // 128
#define TILE_ROWS 8
#define NTILES (ROWS_PER_BLK / TILE_ROWS) // 16
#define STAGES 3
#define TILE_BYTES (TILE_ROWS * H * 4)    // 32768
#define TILE_F4 (TILE_ROWS * H / 4)       // 2048
#define SMEM_DYN (STAGES * TILE_BYTES)    // 98304
#define D_SLICES 64                       // 16 d-rows per slice

// Scratch (no allocations allowed)
__device__ float g_vpart[D_SLICES * H];
__device__ float g_bmax[GRID];
__device__ float g_bsum[GRID];
__device__ float g_v[H];
__device__ unsigned g_bar;   // zero-init; self-resetting
__device__ unsigned g_done;

__device__ __forceinline__ void grid_sync(unsigned target) {
    __syncthreads();
    __threadfence();
    if (threadIdx.x == 0) {
        atomicAdd(&g_bar, 1u);
        while (*(volatile unsigned*)&g_bar < target) __nanosleep(64);
    }
    __syncthreads();
}

__device__ __forceinline__ void mbar_wait(unsigned mbar, unsigned parity) {
    asm volatile(
        "{\n\t"
        ".reg .pred P;\n\t"
        "W_%=:\n\t"
        "mbarrier.try_wait.parity.acquire.cta.shared::cta.b64 P, [%0], %1, 0x989680;\n\t"
        "@P bra D_%=;\n\t"
        "bra W_%=;\n\t"
        "D_%=:\n\t"
        "}" :: "r"(mbar), "r"(parity) : "memory");
}

__global__ __launch_bounds__(BLK, 2) void fused_kernel(
    const float* __restrict__ W,
    const float* __restrict__ hidden,
    const float* __restrict__ enc,
    float* __restrict__ out)
{
    extern __shared__ float4 tile[];                   // [STAGES][TILE_F4]
    __shared__ __align__(8) unsigned long long mbar[STAGES];
    __shared__ float s_sc[ROWS_PER_BLK];
    __shared__ float red[BLK];

    const int tid  = threadIdx.x;
    const int warp = tid >> 5;
    const int lane = tid & 31;
    const int b    = blockIdx.x;

    // mbarrier init (count=1; producer arrives via expect_tx)
    if (tid == 0) {
#pragma unroll
        for (int s = 0; s < STAGES; s++) {
            unsigned a = (unsigned)__cvta_generic_to_shared(&mbar[s]);
            asm volatile("mbarrier.init.shared.b64 [%0], 1;" :: "r"(a) : "memory");
        }
        asm volatile("fence.proxy.async.shared::cta;" ::: "memory");
    }

    // ---------------- P0: v partials (blocks 0..63, coalesced W read) ------
    if (b < D_SLICES) {
        const int d0 = b * (H / D_SLICES);
        float acc0 = 0.f, acc1 = 0.f, acc2 = 0.f, acc3 = 0.f;
#pragma unroll
        for (int dd = 0; dd < H / D_SLICES; dd++) {
            const float hd = __ldg(&hidden[d0 + dd]);
            const float* wr = W + (size_t)(d0 + dd) * H;
            acc0 += wr[tid        ] * hd;
            acc1 += wr[tid +  256 ] * hd;
            acc2 += wr[tid +  512 ] * hd;
            acc3 += wr[tid +  768 ] * hd;
        }
        g_vpart[b * H + tid      ] = acc0;
        g_vpart[b * H + tid + 256] = acc1;
        g_vpart[b * H + tid + 512] = acc2;
        g_vpart[b * H + tid + 768] = acc3;
    }
    grid_sync(GRID);

    // ---------------- P1: reduce partials -> g_v (blocks 0..127) -----------
    if (b < 128) {
        const int h = b * 8 + warp;      // warp per h
        float a = g_vpart[lane * H + h] + g_vpart[(lane + 32) * H + h];
#pragma unroll
        for (int o = 16; o > 0; o >>= 1) a += __shfl_xor_sync(0xFFFFFFFFu, a, o);
        if (lane == 0) g_v[h] = a;
    }
    grid_sync(2 * GRID);

    // ---------------- P2: stream enc via cp.async.bulk pipeline ------------
    // v resident in registers (same lane pattern for every row)
    float4 vr[8];
    const float4* v4 = reinterpret_cast<const float4*>(g_v);
#pragma unroll
    for (int k = 0; k < 8; k++) vr[k] = v4[lane + k * 32];

    const char* src_base = reinterpret_cast<const char*>(enc)
                         + (size_t)b * ROWS_PER_BLK * H * 4;

    if (tid == 0) {
#pragma unroll
        for (int s = 0; s < STAGES; s++) {
            unsigned ba = (unsigned)__cvta_generic_to_shared(&mbar[s]);
            unsigned da = (unsigned)__cvta_generic_to_shared(tile + s * TILE_F4);
            asm volatile("mbarrier.arrive.expect_tx.shared.b64 _, [%0], %1;"
                         :: "r"(ba), "r"(TILE_BYTES) : "memory");
            asm volatile("cp.async.bulk.shared::cta.global.mbarrier::complete_tx::bytes "
                         "[%0], [%1], %2, [%3];"
                         :: "r"(da), "l"(src_base + (size_t)s * TILE_BYTES),
                            "r"(TILE_BYTES), "r"(ba) : "memory");
        }
    }

#pragma unroll 1
    for (int t = 0; t < NTILES; t++) {
        const int st = t % STAGES;
        unsigned ba = (unsigned)__cvta_generic_to_shared(&mbar[st]);
        mbar_wait(ba, (t / STAGES) & 1);

        const float4* rowp = tile + st * TILE_F4 + warp * (H / 4);
        float acc = 0.f;
#pragma unroll
        for (int k = 0; k < 8; k++) {
            float4 e = rowp[lane + k * 32];
            acc += e.x * vr[k].x + e.y * vr[k].y + e.z * vr[k].z + e.w * vr[k].w;
        }
#pragma unroll
        for (int o = 16; o > 0; o >>= 1) acc += __shfl_xor_sync(0xFFFFFFFFu, acc, o);
        if (lane == 0) s_sc[t * TILE_ROWS + warp] = acc;

        __syncthreads();   // all warps done reading stage st
        if (tid == 0 && t + STAGES < NTILES) {
            unsigned da = (unsigned)__cvta_generic_to_shared(tile + st * TILE_F4);
            asm volatile("mbarrier.arrive.expect_tx.shared.b64 _, [%0], %1;"
                         :: "r"(ba), "r"(TILE_BYTES) : "memory");
            asm volatile("cp.async.bulk.shared::cta.global.mbarrier::complete_tx::bytes "
                         "[%0], [%1], %2, [%3];"
                         :: "r"(da), "l"(src_base + (size_t)(t + STAGES) * TILE_BYTES),
                            "r"(TILE_BYTES), "r"(ba) : "memory");
        }
    }

    // block (max, expsum) over its 128 scores
    red[tid] = (tid < ROWS_PER_BLK) ? s_sc[tid] : -CUDART_INF_F;
    __syncthreads();
#pragma unroll
    for (int s = 128; s > 0; s >>= 1) {
        if (tid < s) red[tid] = fmaxf(red[tid], red[tid + s]);
        __syncthreads();
    }
    const float Mb = red[0];
    __syncthreads();
    red[tid] = (tid < ROWS_PER_BLK) ? __expf(s_sc[tid] - Mb) : 0.f;
    __syncthreads();
#pragma unroll
    for (int s = 128; s > 0; s >>= 1) {
        if (tid < s) red[tid] += red[tid + s];
        __syncthreads();
    }
    if (tid == 0) {
        g_bmax[b] = Mb;
        g_bsum[b] = red[0];
    }
    grid_sync(3 * GRID);

    // ---------------- P3: redundant pair-reduce + normalize ----------------
    const float pm = g_bmax[tid];          // GRID == BLK == 256
    const float ps = g_bsum[tid];
    red[tid] = pm;
    __syncthreads();
#pragma unroll
    for (int s = 128; s > 0; s >>= 1) {
        if (tid < s) red[tid] = fmaxf(red[tid], red[tid + s]);
        __syncthreads();
    }
    const float M = red[0];
    __syncthreads();
    red[tid] = ps * __expf(pm - M);
    __syncthreads();
#pragma unroll
    for (int s = 128; s > 0; s >>= 1) {
        if (tid < s) red[tid] += red[tid + s];
        __syncthreads();
    }
    const float inv = 1.0f / red[0];

    if (tid < ROWS_PER_BLK)
        out[b * ROWS_PER_BLK + tid] = __expf(s_sc[tid] - M) * inv;

    // ---------------- reset counters for next graph replay ------------------
    __threadfence();
    __syncthreads();
    if (tid == 0) {
        unsigned d = atomicAdd(&g_done, 1u) + 1;
        if (d == GRID) {
            g_bar = 0;
            g_done = 0;
            __threadfence();
        }
    }
}

// ---------------------------------------------------------------------------
extern "C" void kernel_launch(void* const* d_in, const int* in_sizes, int n_in,
                              void* d_out, int out_size) {
    const float* hidden = (const float*)d_in[0];   // [H]
    const float* enc    = (const float*)d_in[1];   // [S, H]
    const float* W      = (const float*)d_in[2];   // [H, H]
    float* out          = (float*)d_out;           // [S]

    cudaFuncSetAttribute(fused_kernel,
                         cudaFuncAttributeMaxDynamicSharedMemorySize, SMEM_DYN);
    fused_kernel<<<GRID, BLK, SMEM_DYN>>>(W, hidden, enc, out);
}